// round 15
// baseline (speedup 1.0000x reference)
#include <cuda_runtime.h>
#include <cuda_fp16.h>
#include <cstdint>

// MultiHeadAttention: B=2, S=2048, D=1024, H=16, dh=64, fp32.
// R15: all GEMMs 1-pass f16-hi (g_A_l deleted); gemm K-chunk 64 (half the
// syncs); attention kv-chunk 128 (half the softmax overhead), occ 3.
// Error model (validated 3x): ~1.9e-4 per dropped term, RSS; n=12 -> ~6.5e-4.

#define DM 1024
#define NH 16
#define HD 64
#define BB 2
#define SS 2048
#define NTOK (BB * SS)

// ---------------- scratch ----------------
__device__ __half g_Qh[BB*NH*SS*HD];
__device__ __half g_Kh[BB*NH*SS*HD];
__device__ __half g_Vh[BB*NH*SS*HD];
__device__ __half g_Xq_h[NTOK*DM];
__device__ __half g_Xk_h[NTOK*DM];
__device__ __half g_W_h[4*DM*DM];
__device__ __half g_A_h[NTOK*DM];
__device__ uint32_t g_mb[BB*SS*(SS/32)];

__device__ __forceinline__ uint32_t smem_u32(const void* p) {
    uint32_t a;
    asm("{ .reg .u64 t; cvta.to.shared.u64 t, %1; cvt.u32.u64 %0, t; }" : "=r"(a) : "l"(p));
    return a;
}
__device__ __forceinline__ void cpa16(uint32_t s, const void* g) {
    asm volatile("cp.async.cg.shared.global [%0], [%1], 16;" :: "r"(s), "l"(g));
}
#define CP_COMMIT() asm volatile("cp.async.commit_group;" ::: "memory")
#define CP_WAIT(n)  asm volatile("cp.async.wait_group %0;" :: "n"(n) : "memory")
__device__ __forceinline__ void ldmx4(uint32_t* r, uint32_t addr) {
    asm volatile("ldmatrix.sync.aligned.m8n8.x4.shared.b16 {%0,%1,%2,%3}, [%4];"
                 : "=r"(r[0]), "=r"(r[1]), "=r"(r[2]), "=r"(r[3]) : "r"(addr));
}
__device__ __forceinline__ void ldmx4t(uint32_t* r, uint32_t addr) {
    asm volatile("ldmatrix.sync.aligned.m8n8.x4.trans.shared.b16 {%0,%1,%2,%3}, [%4];"
                 : "=r"(r[0]), "=r"(r[1]), "=r"(r[2]), "=r"(r[3]) : "r"(addr));
}
__device__ __forceinline__ void mma_f32(float* c, const uint32_t* a, const uint32_t* b) {
    asm volatile(
        "mma.sync.aligned.m16n8k16.row.col.f32.f16.f16.f32 "
        "{%0,%1,%2,%3}, {%4,%5,%6,%7}, {%8,%9}, {%0,%1,%2,%3};"
        : "+f"(c[0]), "+f"(c[1]), "+f"(c[2]), "+f"(c[3])
        : "r"(a[0]), "r"(a[1]), "r"(a[2]), "r"(a[3]), "r"(b[0]), "r"(b[1]));
}
__device__ __forceinline__ uint32_t pack_h(float a, float b) {
    __half2 hv = __halves2half2(__float2half_rn(a), __float2half_rn(b));
    return *reinterpret_cast<uint32_t*>(&hv);
}

// ---------------- fp32 -> f16 ----------------
__global__ __launch_bounds__(256) void split_x(const float* __restrict__ Xq,
                                               const float* __restrict__ Xkv)
{
    int i = blockIdx.x * 256 + threadIdx.x;
    const float* src = (blockIdx.y == 0) ? Xq : Xkv;
    __half* dst = (blockIdx.y == 0) ? g_Xq_h : g_Xk_h;
    float4 v = ((const float4*)src)[i];
    __half2* H = (__half2*)(dst + (size_t)i * 4);
    H[0] = __halves2half2(__float2half_rn(v.x), __float2half_rn(v.y));
    H[1] = __halves2half2(__float2half_rn(v.z), __float2half_rn(v.w));
}
__global__ __launch_bounds__(256) void split_w(
    const float* __restrict__ Wq, const float* __restrict__ Wk,
    const float* __restrict__ Wv, const float* __restrict__ Wo)
{
    int i = blockIdx.x * 256 + threadIdx.x;
    int z = blockIdx.y;
    const float* src = (z == 0) ? Wq : (z == 1) ? Wk : (z == 2) ? Wv : Wo;
    __half* dst = g_W_h + (size_t)z * DM * DM;
    float4 v = ((const float4*)src)[i];
    __half2* H = (__half2*)(dst + (size_t)i * 4);
    H[0] = __halves2half2(__float2half_rn(v.x), __float2half_rn(v.y));
    H[1] = __halves2half2(__float2half_rn(v.z), __float2half_rn(v.w));
}

// ---------------- mask -> bitmask ----------------
__global__ __launch_bounds__(256) void mask_pack(const int* __restrict__ mask)
{
    int idx = blockIdx.x * 256 + threadIdx.x;
    const int4* src = (const int4*)(mask + (size_t)idx * 32);
    uint32_t bits = 0;
#pragma unroll
    for (int j = 0; j < 8; j++) {
        int4 v = src[j];
        bits |= (v.x ? 1u : 0u) << (j * 4);
        bits |= (v.y ? 1u : 0u) << (j * 4 + 1);
        bits |= (v.z ? 1u : 0u) << (j * 4 + 2);
        bits |= (v.w ? 1u : 0u) << (j * 4 + 3);
    }
    g_mb[idx] = bits;
}

// ---------------- 1-pass HMMA GEMM, K-chunk 64 ----------------
// A, B tiles: 128 rows x 128B (64 f16), 8-unit swizzle. Stage 32KB x2 = 64KB.
__device__ __forceinline__ void gemm1_load_chunk(
    uint32_t sb, int st, const __half* Ah, const __half* Bh,
    int m0, int n0, int kt, int tid)
{
    const uint32_t ab = sb + st * 32768;
    const uint32_t bbp = ab + 16384;
    const int r = tid >> 1, half = tid & 1;
    const size_t arow = (size_t)(m0 + r) * DM + kt;
    const size_t brow = (size_t)(n0 + r) * DM + kt;
#pragma unroll
    for (int q = 0; q < 4; q++) {
        const int u = half * 4 + q;
        const uint32_t off = r * 128 + (((u ^ (r & 7)) & 7) << 4);
        cpa16(ab + off,  Ah + arow + u * 8);
        cpa16(bbp + off, Bh + brow + u * 8);
    }
}

// mode 0: fp32 flat out; mode 2: f16-hi to Ch [b][h][s][d]
__device__ __forceinline__ void gemm1_body(
    const __half* __restrict__ Ah, const __half* __restrict__ Bh,
    const float* __restrict__ bias, float* __restrict__ C,
    __half* __restrict__ Ch, int mode, char* smem)
{
    const uint32_t sb = smem_u32(smem);
    const int tid = threadIdx.x, lane = tid & 31, wid = tid >> 5;
    const int wm = wid & 3, wn = wid >> 2;
    const int m0 = blockIdx.y * 128, n0 = blockIdx.x * 128;

    float acc[2][8][4] = {};

    const int a_rp = (lane & 7) + ((lane >> 3) & 1) * 8;
    const int a_up = (lane >> 4);
    const int b_rp = (lane & 7) + ((lane >> 4) << 3);
    const int b_up = (lane >> 3) & 1;

    const int NC = DM / 64;   // 16 chunks
    gemm1_load_chunk(sb, 0, Ah, Bh, m0, n0, 0, tid);
    CP_COMMIT();

    for (int c = 0; c < NC; c++) {
        if (c + 1 < NC) {
            gemm1_load_chunk(sb, (c + 1) & 1, Ah, Bh, m0, n0, (c + 1) * 64, tid);
            CP_COMMIT();
            CP_WAIT(1);
        } else {
            CP_WAIT(0);
        }
        __syncthreads();

        const uint32_t ab = sb + (c & 1) * 32768;
        const uint32_t bbp = ab + 16384;
#pragma unroll
        for (int ks = 0; ks < 4; ks++) {
            uint32_t ah[2][4];
#pragma unroll
            for (int ma = 0; ma < 2; ma++) {
                int row = wm * 32 + ma * 16 + a_rp;
                int u = (ks * 2 + a_up) ^ (row & 7);
                ldmx4(ah[ma], ab + (uint32_t)(row * 128 + u * 16));
            }
#pragma unroll
            for (int p = 0; p < 4; p++) {
                int row = wn * 64 + p * 16 + b_rp;
                int u = (ks * 2 + b_up) ^ (row & 7);
                uint32_t bb[4];
                ldmx4(bb, bbp + (uint32_t)(row * 128 + u * 16));
#pragma unroll
                for (int ma = 0; ma < 2; ma++) {
                    mma_f32(acc[ma][2 * p],     ah[ma], &bb[0]);
                    mma_f32(acc[ma][2 * p + 1], ah[ma], &bb[2]);
                }
            }
        }
        __syncthreads();
    }

#pragma unroll
    for (int ma = 0; ma < 2; ma++) {
#pragma unroll
        for (int rh = 0; rh < 2; rh++) {
            const int m = m0 + wm * 32 + ma * 16 + (lane >> 2) + rh * 8;
            const int bbi = m >> 11, sIdx = m & (SS - 1);
#pragma unroll
            for (int na = 0; na < 8; na++) {
                const int e = n0 + wn * 64 + na * 8 + 2 * (lane & 3);
                float v0 = acc[ma][na][rh * 2 + 0] + bias[e];
                float v1 = acc[ma][na][rh * 2 + 1] + bias[e + 1];
                if (mode == 0) {
                    *(float2*)&C[(size_t)m * DM + e] = make_float2(v0, v1);
                } else {
                    int hh = e >> 6, dd = e & 63;
                    size_t base = (((size_t)(bbi * NH + hh)) * SS + sIdx) * HD + dd;
                    *(uint32_t*)(Ch + base) = pack_h(v0, v1);
                }
            }
        }
    }
}

__global__ __launch_bounds__(256, 2) void gemm_qkv(const float* __restrict__ bq,
                                                   const float* __restrict__ bk,
                                                   const float* __restrict__ bv)
{
    extern __shared__ char smem[];
    const int z = blockIdx.z;
    const __half* Ah = (z == 0) ? g_Xq_h : g_Xk_h;
    const __half* Bh = g_W_h + (size_t)z * DM * DM;
    const float* bias = (z == 0) ? bq : (z == 1) ? bk : bv;
    __half* Ch = (z == 0) ? g_Qh : (z == 1) ? g_Kh : g_Vh;
    gemm1_body(Ah, Bh, bias, nullptr, Ch, 2, smem);
}

__global__ __launch_bounds__(256, 2) void gemm_o(const float* __restrict__ bo,
                                                 float* __restrict__ out)
{
    extern __shared__ char smem[];
    gemm1_body(g_A_h, g_W_h + (size_t)3 * DM * DM, bo, out, nullptr, 0, smem);
}

// ---------------- HMMA flash attention, kv-chunk 128, 2-stage, 1-pass --------
// smem: Q 8KB at 0; stage st: K at 8192+st*32768, V at +16384. Total 73728.
__device__ __forceinline__ void attn_load_chunk(
    uint32_t sb, int st, const __half* Khg, const __half* Vhg, int kv0, int tid)
{
    const int row = tid;   // 128 rows, one per thread
    const uint32_t kb = sb + 8192 + st * 32768;
    const uint32_t vb = kb + 16384;
    const size_t gro = (size_t)(kv0 + row) * HD;
    const uint4* pk = (const uint4*)(Khg + gro);
    const uint4* pv = (const uint4*)(Vhg + gro);
#pragma unroll
    for (int q = 0; q < 8; q++) {
        const uint32_t off = row * 128 + ((q ^ (row & 7)) << 4);
        cpa16(kb + off, pk + q);
        cpa16(vb + off, pv + q);
    }
}

__global__ __launch_bounds__(128, 3) void attn_tc()
{
    extern __shared__ char smem[];
    const uint32_t sb = smem_u32(smem);

    const int tid = threadIdx.x, lane = tid & 31, wid = tid >> 5;
    const int bh = blockIdx.y, b = bh >> 4, h = bh & 15;
    const int q0 = blockIdx.x * 64;

    const __half* Khg = g_Kh + (size_t)bh * SS * HD;
    const __half* Vhg = g_Vh + (size_t)bh * SS * HD;

    {
        const int r = tid >> 1, half = tid & 1;
        const __half* qh = g_Qh + ((size_t)bh * SS + q0 + r) * HD + half * 32;
#pragma unroll
        for (int q = 0; q < 4; q++) {
            uint32_t off = r * 128 + ((((half * 4 + q) ^ (r & 7)) & 7) << 4);
            cpa16(sb + off, ((const uint4*)qh) + q);
        }
    }
    CP_COMMIT();
    attn_load_chunk(sb, 0, Khg, Vhg, 0, tid);
    CP_COMMIT();
    CP_WAIT(1);
    __syncthreads();

    const int a_rp = (lane & 7) + ((lane >> 3) & 1) * 8;
    const int a_up = (lane >> 4);
    const int b_rp = (lane & 7) + ((lane >> 4) << 3);
    const int b_up = (lane >> 3) & 1;

    uint32_t qah[4][4];
#pragma unroll
    for (int kc = 0; kc < 4; kc++) {
        int row = wid * 16 + a_rp;
        int u = (kc * 2 + a_up) ^ (row & 7);
        ldmx4(qah[kc], sb + (uint32_t)(row * 128 + u * 16));
    }

    float acc[8][4] = {};
    float m0 = -1e30f, m1 = -1e30f, l0 = 0.f, l1 = 0.f;
    const int gq0 = q0 + wid * 16 + (lane >> 2);
    const int gq1 = gq0 + 8;
    const uint32_t* mrow0 = g_mb + ((size_t)(b * SS) + gq0) * 64;
    const uint32_t* mrow1 = g_mb + ((size_t)(b * SS) + gq1) * 64;

    const int NC = SS / 128;   // 16 chunks
    for (int c = 0; c < NC; c++) {
        if (c + 1 < NC) {
            attn_load_chunk(sb, (c + 1) & 1, Khg, Vhg, (c + 1) * 128, tid);
            CP_COMMIT();
            CP_WAIT(1);
        } else {
            CP_WAIT(0);
        }
        __syncthreads();

        const uint32_t kbase = sb + 8192 + (c & 1) * 32768;
        const uint32_t vbase = kbase + 16384;

        // S = Qh Kh^T (16 x 128 per warp)
        float s[16][4] = {};
#pragma unroll
        for (int kc = 0; kc < 4; kc++) {
#pragma unroll
            for (int p = 0; p < 8; p++) {
                int row = p * 16 + b_rp;
                int u = (kc * 2 + b_up) ^ (row & 7);
                uint32_t kb[4];
                ldmx4(kb, kbase + (uint32_t)(row * 128 + u * 16));
                mma_f32(s[2 * p],     qah[kc], &kb[0]);
                mma_f32(s[2 * p + 1], qah[kc], &kb[2]);
            }
        }

        // mask + scale
        {
            const int wb = c * 4;
            uint32_t w0[4], w1[4];
#pragma unroll
            for (int j = 0; j < 4; j++) { w0[j] = mrow0[wb + j]; w1[j] = mrow1[wb + j]; }
            uint32_t allm = w0[0] & w0[1] & w0[2] & w0[3] & w1[0] & w1[1] & w1[2] & w1[3];
            if (allm == 0xFFFFFFFFu) {
#pragma unroll
                for (int t = 0; t < 16; t++) {
                    s[t][0] *= 0.125f; s[t][1] *= 0.125f;
                    s[t][2] *= 0.125f; s[t][3] *= 0.125f;
                }
            } else {
#pragma unroll
                for (int t = 0; t < 16; t++) {
                    int c0 = t * 8 + 2 * (lane & 3), c1 = c0 + 1;
                    s[t][0] = ((w0[c0 >> 5] >> (c0 & 31)) & 1) ? s[t][0] * 0.125f : -1e9f;
                    s[t][1] = ((w0[c1 >> 5] >> (c1 & 31)) & 1) ? s[t][1] * 0.125f : -1e9f;
                    s[t][2] = ((w1[c0 >> 5] >> (c0 & 31)) & 1) ? s[t][2] * 0.125f : -1e9f;
                    s[t][3] = ((w1[c1 >> 5] >> (c1 & 31)) & 1) ? s[t][3] * 0.125f : -1e9f;
                }
            }
        }

        // online softmax (once per 128 kv)
        {
            float mx0 = -1e30f, mx1 = -1e30f;
#pragma unroll
            for (int t = 0; t < 16; t++) {
                mx0 = fmaxf(mx0, fmaxf(s[t][0], s[t][1]));
                mx1 = fmaxf(mx1, fmaxf(s[t][2], s[t][3]));
            }
            mx0 = fmaxf(mx0, __shfl_xor_sync(0xffffffffu, mx0, 1));
            mx0 = fmaxf(mx0, __shfl_xor_sync(0xffffffffu, mx0, 2));
            mx1 = fmaxf(mx1, __shfl_xor_sync(0xffffffffu, mx1, 1));
            mx1 = fmaxf(mx1, __shfl_xor_sync(0xffffffffu, mx1, 2));
            float mn0 = fmaxf(m0, mx0), mn1 = fmaxf(m1, mx1);
            float c0f = __expf(m0 - mn0), c1f = __expf(m1 - mn1);
            m0 = mn0; m1 = mn1;
            float ls0 = 0.f, ls1 = 0.f;
#pragma unroll
            for (int t = 0; t < 16; t++) {
                s[t][0] = __expf(s[t][0] - mn0); ls0 += s[t][0];
                s[t][1] = __expf(s[t][1] - mn0); ls0 += s[t][1];
                s[t][2] = __expf(s[t][2] - mn1); ls1 += s[t][2];
                s[t][3] = __expf(s[t][3] - mn1); ls1 += s[t][3];
            }
            l0 = l0 * c0f + ls0; l1 = l1 * c1f + ls1;
#pragma unroll
            for (int t = 0; t < 8; t++) {
                acc[t][0] *= c0f; acc[t][1] *= c0f;
                acc[t][2] *= c1f; acc[t][3] *= c1f;
            }
        }

        // O += Ph V (register-direct P)
#pragma unroll
        for (int kc = 0; kc < 8; kc++) {
            uint32_t pah[4];
            pah[0] = pack_h(s[2 * kc][0],     s[2 * kc][1]);
            pah[1] = pack_h(s[2 * kc][2],     s[2 * kc][3]);
            pah[2] = pack_h(s[2 * kc + 1][0], s[2 * kc + 1][1]);
            pah[3] = pack_h(s[2 * kc + 1][2], s[2 * kc + 1][3]);
            const int vrow = kc * 16 + (((lane >> 3) & 1) << 3) + (lane & 7);
            const int vup = lane >> 4;
#pragma unroll
            for (int g = 0; g < 4; g++) {
                int u = (g * 2 + vup) ^ (vrow & 7);
                uint32_t off = (uint32_t)(vrow * 128 + u * 16);
                uint32_t vb[4];
                ldmx4t(vb, vbase + off);
                mma_f32(acc[2 * g],     pah, &vb[0]);
                mma_f32(acc[2 * g + 1], pah, &vb[2]);
            }
        }
        __syncthreads();
    }

    l0 += __shfl_xor_sync(0xffffffffu, l0, 1);
    l0 += __shfl_xor_sync(0xffffffffu, l0, 2);
    l1 += __shfl_xor_sync(0xffffffffu, l1, 1);
    l1 += __shfl_xor_sync(0xffffffffu, l1, 2);
    const float inv0 = 1.f / l0, inv1 = 1.f / l1;
    const size_t o0 = ((size_t)(b * SS) + gq0) * DM + h * HD;
    const size_t o1 = ((size_t)(b * SS) + gq1) * DM + h * HD;
#pragma unroll
    for (int t = 0; t < 8; t++) {
        int d = t * 8 + 2 * (lane & 3);
        *(uint32_t*)(g_A_h + o0 + d) = pack_h(acc[t][0] * inv0, acc[t][1] * inv0);
        *(uint32_t*)(g_A_h + o1 + d) = pack_h(acc[t][2] * inv1, acc[t][3] * inv1);
    }
}

static const int GEMM_SMEM = 65536;
static const int ATTN_SMEM = 73728;

extern "C" void kernel_launch(void* const* d_in, const int* in_sizes, int n_in,
                              void* d_out, int out_size)
{
    const float* Xq  = (const float*)d_in[0];
    const float* Xkv = (const float*)d_in[1];
    const int*   msk = (const int*)d_in[2];
    const float* Wq  = (const float*)d_in[3];
    const float* bq  = (const float*)d_in[4];
    const float* Wk  = (const float*)d_in[5];
    const float* bk  = (const float*)d_in[6];
    const float* Wv  = (const float*)d_in[7];
    const float* bv  = (const float*)d_in[8];
    const float* Wo  = (const float*)d_in[9];
    const float* bo  = (const float*)d_in[10];
    float* out = (float*)d_out;

    cudaFuncSetAttribute(gemm_qkv, cudaFuncAttributeMaxDynamicSharedMemorySize, GEMM_SMEM);
    cudaFuncSetAttribute(gemm_o,   cudaFuncAttributeMaxDynamicSharedMemorySize, GEMM_SMEM);
    cudaFuncSetAttribute(attn_tc,  cudaFuncAttributeMaxDynamicSharedMemorySize, ATTN_SMEM);

    const int n4x = NTOK * DM / 4;
    const int n4w = DM * DM / 4;

    split_x<<<dim3(n4x / 256, 2), 256>>>(Xq, Xkv);
    split_w<<<dim3(n4w / 256, 4), 256>>>(Wq, Wk, Wv, Wo);
    mask_pack<<<BB * SS * (SS / 32) / 256, 256>>>(msk);

    gemm_qkv<<<dim3(DM / 128, NTOK / 128, 3), 256, GEMM_SMEM>>>(bq, bk, bv);
    attn_tc<<<dim3(SS / 64, BB * NH), 128, ATTN_SMEM>>>();
    gemm_o<<<dim3(DM / 128, NTOK / 128), 256, GEMM_SMEM>>>(bo, out);
}

// round 16
// speedup vs baseline: 1.1986x; 1.1986x over previous
#include <cuda_runtime.h>
#include <cuda_fp16.h>
#include <cstdint>

// MultiHeadAttention: B=2, S=2048, D=1024, H=16, dh=64, fp32.
// R16: recombination of measured winners. Attention = R14's (kv-chunk 64,
// 40KB smem, occ 3, ~170us measured). GEMMs = R15's (K-chunk 64 qkv at
// 106.6us; 1-pass gemm_o). R15's kv-chunk-128 attn regressed (occ drop) and
// is reverted. All mma 1-pass f16-hi except none; error n=12 -> ~6.5e-4.

#define DM 1024
#define NH 16
#define HD 64
#define BB 2
#define SS 2048
#define NTOK (BB * SS)

// ---------------- scratch ----------------
__device__ __half g_Qh[BB*NH*SS*HD];
__device__ __half g_Kh[BB*NH*SS*HD];
__device__ __half g_Vh[BB*NH*SS*HD];
__device__ __half g_Xq_h[NTOK*DM];
__device__ __half g_Xk_h[NTOK*DM];
__device__ __half g_W_h[4*DM*DM];
__device__ __half g_A_h[NTOK*DM];
__device__ uint32_t g_mb[BB*SS*(SS/32)];

__device__ __forceinline__ uint32_t smem_u32(const void* p) {
    uint32_t a;
    asm("{ .reg .u64 t; cvta.to.shared.u64 t, %1; cvt.u32.u64 %0, t; }" : "=r"(a) : "l"(p));
    return a;
}
__device__ __forceinline__ void cpa16(uint32_t s, const void* g) {
    asm volatile("cp.async.cg.shared.global [%0], [%1], 16;" :: "r"(s), "l"(g));
}
#define CP_COMMIT() asm volatile("cp.async.commit_group;" ::: "memory")
#define CP_WAIT(n)  asm volatile("cp.async.wait_group %0;" :: "n"(n) : "memory")
__device__ __forceinline__ void ldmx4(uint32_t* r, uint32_t addr) {
    asm volatile("ldmatrix.sync.aligned.m8n8.x4.shared.b16 {%0,%1,%2,%3}, [%4];"
                 : "=r"(r[0]), "=r"(r[1]), "=r"(r[2]), "=r"(r[3]) : "r"(addr));
}
__device__ __forceinline__ void ldmx4t(uint32_t* r, uint32_t addr) {
    asm volatile("ldmatrix.sync.aligned.m8n8.x4.trans.shared.b16 {%0,%1,%2,%3}, [%4];"
                 : "=r"(r[0]), "=r"(r[1]), "=r"(r[2]), "=r"(r[3]) : "r"(addr));
}
__device__ __forceinline__ void mma_f32(float* c, const uint32_t* a, const uint32_t* b) {
    asm volatile(
        "mma.sync.aligned.m16n8k16.row.col.f32.f16.f16.f32 "
        "{%0,%1,%2,%3}, {%4,%5,%6,%7}, {%8,%9}, {%0,%1,%2,%3};"
        : "+f"(c[0]), "+f"(c[1]), "+f"(c[2]), "+f"(c[3])
        : "r"(a[0]), "r"(a[1]), "r"(a[2]), "r"(a[3]), "r"(b[0]), "r"(b[1]));
}
__device__ __forceinline__ uint32_t pack_h(float a, float b) {
    __half2 hv = __halves2half2(__float2half_rn(a), __float2half_rn(b));
    return *reinterpret_cast<uint32_t*>(&hv);
}

// ---------------- fp32 -> f16 ----------------
__global__ __launch_bounds__(256) void split_x(const float* __restrict__ Xq,
                                               const float* __restrict__ Xkv)
{
    int i = blockIdx.x * 256 + threadIdx.x;
    const float* src = (blockIdx.y == 0) ? Xq : Xkv;
    __half* dst = (blockIdx.y == 0) ? g_Xq_h : g_Xk_h;
    float4 v = ((const float4*)src)[i];
    __half2* H = (__half2*)(dst + (size_t)i * 4);
    H[0] = __halves2half2(__float2half_rn(v.x), __float2half_rn(v.y));
    H[1] = __halves2half2(__float2half_rn(v.z), __float2half_rn(v.w));
}
__global__ __launch_bounds__(256) void split_w(
    const float* __restrict__ Wq, const float* __restrict__ Wk,
    const float* __restrict__ Wv, const float* __restrict__ Wo)
{
    int i = blockIdx.x * 256 + threadIdx.x;
    int z = blockIdx.y;
    const float* src = (z == 0) ? Wq : (z == 1) ? Wk : (z == 2) ? Wv : Wo;
    __half* dst = g_W_h + (size_t)z * DM * DM;
    float4 v = ((const float4*)src)[i];
    __half2* H = (__half2*)(dst + (size_t)i * 4);
    H[0] = __halves2half2(__float2half_rn(v.x), __float2half_rn(v.y));
    H[1] = __halves2half2(__float2half_rn(v.z), __float2half_rn(v.w));
}

// ---------------- mask -> bitmask ----------------
__global__ __launch_bounds__(256) void mask_pack(const int* __restrict__ mask)
{
    int idx = blockIdx.x * 256 + threadIdx.x;
    const int4* src = (const int4*)(mask + (size_t)idx * 32);
    uint32_t bits = 0;
#pragma unroll
    for (int j = 0; j < 8; j++) {
        int4 v = src[j];
        bits |= (v.x ? 1u : 0u) << (j * 4);
        bits |= (v.y ? 1u : 0u) << (j * 4 + 1);
        bits |= (v.z ? 1u : 0u) << (j * 4 + 2);
        bits |= (v.w ? 1u : 0u) << (j * 4 + 3);
    }
    g_mb[idx] = bits;
}

// ---------------- 1-pass HMMA GEMM, K-chunk 64 (R15, kept) ----------------
__device__ __forceinline__ void gemm1_load_chunk(
    uint32_t sb, int st, const __half* Ah, const __half* Bh,
    int m0, int n0, int kt, int tid)
{
    const uint32_t ab = sb + st * 32768;
    const uint32_t bbp = ab + 16384;
    const int r = tid >> 1, half = tid & 1;
    const size_t arow = (size_t)(m0 + r) * DM + kt;
    const size_t brow = (size_t)(n0 + r) * DM + kt;
#pragma unroll
    for (int q = 0; q < 4; q++) {
        const int u = half * 4 + q;
        const uint32_t off = r * 128 + (((u ^ (r & 7)) & 7) << 4);
        cpa16(ab + off,  Ah + arow + u * 8);
        cpa16(bbp + off, Bh + brow + u * 8);
    }
}

__device__ __forceinline__ void gemm1_body(
    const __half* __restrict__ Ah, const __half* __restrict__ Bh,
    const float* __restrict__ bias, float* __restrict__ C,
    __half* __restrict__ Ch, int mode, char* smem)
{
    const uint32_t sb = smem_u32(smem);
    const int tid = threadIdx.x, lane = tid & 31, wid = tid >> 5;
    const int wm = wid & 3, wn = wid >> 2;
    const int m0 = blockIdx.y * 128, n0 = blockIdx.x * 128;

    float acc[2][8][4] = {};

    const int a_rp = (lane & 7) + ((lane >> 3) & 1) * 8;
    const int a_up = (lane >> 4);
    const int b_rp = (lane & 7) + ((lane >> 4) << 3);
    const int b_up = (lane >> 3) & 1;

    const int NC = DM / 64;
    gemm1_load_chunk(sb, 0, Ah, Bh, m0, n0, 0, tid);
    CP_COMMIT();

    for (int c = 0; c < NC; c++) {
        if (c + 1 < NC) {
            gemm1_load_chunk(sb, (c + 1) & 1, Ah, Bh, m0, n0, (c + 1) * 64, tid);
            CP_COMMIT();
            CP_WAIT(1);
        } else {
            CP_WAIT(0);
        }
        __syncthreads();

        const uint32_t ab = sb + (c & 1) * 32768;
        const uint32_t bbp = ab + 16384;
#pragma unroll
        for (int ks = 0; ks < 4; ks++) {
            uint32_t ah[2][4];
#pragma unroll
            for (int ma = 0; ma < 2; ma++) {
                int row = wm * 32 + ma * 16 + a_rp;
                int u = (ks * 2 + a_up) ^ (row & 7);
                ldmx4(ah[ma], ab + (uint32_t)(row * 128 + u * 16));
            }
#pragma unroll
            for (int p = 0; p < 4; p++) {
                int row = wn * 64 + p * 16 + b_rp;
                int u = (ks * 2 + b_up) ^ (row & 7);
                uint32_t bb[4];
                ldmx4(bb, bbp + (uint32_t)(row * 128 + u * 16));
#pragma unroll
                for (int ma = 0; ma < 2; ma++) {
                    mma_f32(acc[ma][2 * p],     ah[ma], &bb[0]);
                    mma_f32(acc[ma][2 * p + 1], ah[ma], &bb[2]);
                }
            }
        }
        __syncthreads();
    }

#pragma unroll
    for (int ma = 0; ma < 2; ma++) {
#pragma unroll
        for (int rh = 0; rh < 2; rh++) {
            const int m = m0 + wm * 32 + ma * 16 + (lane >> 2) + rh * 8;
            const int bbi = m >> 11, sIdx = m & (SS - 1);
#pragma unroll
            for (int na = 0; na < 8; na++) {
                const int e = n0 + wn * 64 + na * 8 + 2 * (lane & 3);
                float v0 = acc[ma][na][rh * 2 + 0] + bias[e];
                float v1 = acc[ma][na][rh * 2 + 1] + bias[e + 1];
                if (mode == 0) {
                    *(float2*)&C[(size_t)m * DM + e] = make_float2(v0, v1);
                } else {
                    int hh = e >> 6, dd = e & 63;
                    size_t base = (((size_t)(bbi * NH + hh)) * SS + sIdx) * HD + dd;
                    *(uint32_t*)(Ch + base) = pack_h(v0, v1);
                }
            }
        }
    }
}

__global__ __launch_bounds__(256, 2) void gemm_qkv(const float* __restrict__ bq,
                                                   const float* __restrict__ bk,
                                                   const float* __restrict__ bv)
{
    extern __shared__ char smem[];
    const int z = blockIdx.z;
    const __half* Ah = (z == 0) ? g_Xq_h : g_Xk_h;
    const __half* Bh = g_W_h + (size_t)z * DM * DM;
    const float* bias = (z == 0) ? bq : (z == 1) ? bk : bv;
    __half* Ch = (z == 0) ? g_Qh : (z == 1) ? g_Kh : g_Vh;
    gemm1_body(Ah, Bh, bias, nullptr, Ch, 2, smem);
}

__global__ __launch_bounds__(256, 2) void gemm_o(const float* __restrict__ bo,
                                                 float* __restrict__ out)
{
    extern __shared__ char smem[];
    gemm1_body(g_A_h, g_W_h + (size_t)3 * DM * DM, bo, out, nullptr, 0, smem);
}

// ---------------- HMMA flash attention, kv-chunk 64, 2-stage, 1-pass (R14) ----
// smem: Q 8KB at 0; stage st: K at 8192+st*16384, V at +8192. Total 40960.
__device__ __forceinline__ void attn_load_chunk(
    uint32_t sb, int st, const __half* Khg, const __half* Vhg, int kv0, int tid)
{
    const int r = tid >> 1, half = tid & 1;
    const uint32_t kb = sb + 8192 + st * 16384;
    const uint32_t vb = kb + 8192;
    const size_t gro = (size_t)(kv0 + r) * HD + half * 32;
#pragma unroll
    for (int q = 0; q < 4; q++) {
        const uint32_t off = r * 128 + ((((half * 4 + q) ^ (r & 7)) & 7) << 4);
        cpa16(kb + off, ((const uint4*)(Khg + gro)) + q);
        cpa16(vb + off, ((const uint4*)(Vhg + gro)) + q);
    }
}

__global__ __launch_bounds__(128, 3) void attn_tc()
{
    extern __shared__ char smem[];
    const uint32_t sb = smem_u32(smem);

    const int tid = threadIdx.x, lane = tid & 31, wid = tid >> 5;
    const int bh = blockIdx.y, b = bh >> 4, h = bh & 15;
    const int q0 = blockIdx.x * 64;

    const __half* Khg = g_Kh + (size_t)bh * SS * HD;
    const __half* Vhg = g_Vh + (size_t)bh * SS * HD;

    {
        const int r = tid >> 1, half = tid & 1;
        const __half* qh = g_Qh + ((size_t)bh * SS + q0 + r) * HD + half * 32;
#pragma unroll
        for (int q = 0; q < 4; q++) {
            uint32_t off = r * 128 + ((((half * 4 + q) ^ (r & 7)) & 7) << 4);
            cpa16(sb + off, ((const uint4*)qh) + q);
        }
    }
    CP_COMMIT();
    attn_load_chunk(sb, 0, Khg, Vhg, 0, tid);
    CP_COMMIT();
    CP_WAIT(1);
    __syncthreads();

    const int a_rp = (lane & 7) + ((lane >> 3) & 1) * 8;
    const int a_up = (lane >> 4);
    const int b_rp = (lane & 7) + ((lane >> 4) << 3);
    const int b_up = (lane >> 3) & 1;

    uint32_t qah[4][4];
#pragma unroll
    for (int kc = 0; kc < 4; kc++) {
        int row = wid * 16 + a_rp;
        int u = (kc * 2 + a_up) ^ (row & 7);
        ldmx4(qah[kc], sb + (uint32_t)(row * 128 + u * 16));
    }

    float acc[8][4] = {};
    float m0 = -1e30f, m1 = -1e30f, l0 = 0.f, l1 = 0.f;
    const int gq0 = q0 + wid * 16 + (lane >> 2);
    const int gq1 = gq0 + 8;
    const uint32_t* mrow0 = g_mb + ((size_t)(b * SS) + gq0) * 64;
    const uint32_t* mrow1 = g_mb + ((size_t)(b * SS) + gq1) * 64;

    const int NC = SS / 64;
    for (int c = 0; c < NC; c++) {
        if (c + 1 < NC) {
            attn_load_chunk(sb, (c + 1) & 1, Khg, Vhg, (c + 1) * 64, tid);
            CP_COMMIT();
            CP_WAIT(1);
        } else {
            CP_WAIT(0);
        }
        __syncthreads();

        const uint32_t kbase = sb + 8192 + (c & 1) * 16384;
        const uint32_t vbase = kbase + 8192;

        float s[8][4] = {};
#pragma unroll
        for (int kc = 0; kc < 4; kc++) {
#pragma unroll
            for (int p = 0; p < 4; p++) {
                int row = p * 16 + b_rp;
                uint32_t kb[4];
                ldmx4(kb, kbase + (uint32_t)(row * 128) +
                          (((kc * 2 + b_up) ^ (row & 7)) << 4));
                mma_f32(s[2 * p],     qah[kc], &kb[0]);
                mma_f32(s[2 * p + 1], qah[kc], &kb[2]);
            }
        }

        {
            const int wb = c * 2;
            uint32_t w0[2], w1[2];
            w0[0] = mrow0[wb]; w0[1] = mrow0[wb + 1];
            w1[0] = mrow1[wb]; w1[1] = mrow1[wb + 1];
            uint32_t allm = w0[0] & w0[1] & w1[0] & w1[1];
            if (allm == 0xFFFFFFFFu) {
#pragma unroll
                for (int t = 0; t < 8; t++) {
                    s[t][0] *= 0.125f; s[t][1] *= 0.125f;
                    s[t][2] *= 0.125f; s[t][3] *= 0.125f;
                }
            } else {
#pragma unroll
                for (int t = 0; t < 8; t++) {
                    int c0 = t * 8 + 2 * (lane & 3), c1 = c0 + 1;
                    s[t][0] = ((w0[c0 >> 5] >> (c0 & 31)) & 1) ? s[t][0] * 0.125f : -1e9f;
                    s[t][1] = ((w0[c1 >> 5] >> (c1 & 31)) & 1) ? s[t][1] * 0.125f : -1e9f;
                    s[t][2] = ((w1[c0 >> 5] >> (c0 & 31)) & 1) ? s[t][2] * 0.125f : -1e9f;
                    s[t][3] = ((w1[c1 >> 5] >> (c1 & 31)) & 1) ? s[t][3] * 0.125f : -1e9f;
                }
            }
        }

        {
            float mx0 = -1e30f, mx1 = -1e30f;
#pragma unroll
            for (int t = 0; t < 8; t++) {
                mx0 = fmaxf(mx0, fmaxf(s[t][0], s[t][1]));
                mx1 = fmaxf(mx1, fmaxf(s[t][2], s[t][3]));
            }
            mx0 = fmaxf(mx0, __shfl_xor_sync(0xffffffffu, mx0, 1));
            mx0 = fmaxf(mx0, __shfl_xor_sync(0xffffffffu, mx0, 2));
            mx1 = fmaxf(mx1, __shfl_xor_sync(0xffffffffu, mx1, 1));
            mx1 = fmaxf(mx1, __shfl_xor_sync(0xffffffffu, mx1, 2));
            float mn0 = fmaxf(m0, mx0), mn1 = fmaxf(m1, mx1);
            float c0f = __expf(m0 - mn0), c1f = __expf(m1 - mn1);
            m0 = mn0; m1 = mn1;
            float ls0 = 0.f, ls1 = 0.f;
#pragma unroll
            for (int t = 0; t < 8; t++) {
                s[t][0] = __expf(s[t][0] - mn0); ls0 += s[t][0];
                s[t][1] = __expf(s[t][1] - mn0); ls0 += s[t][1];
                s[t][2] = __expf(s[t][2] - mn1); ls1 += s[t][2];
                s[t][3] = __expf(s[t][3] - mn1); ls1 += s[t][3];
            }
            l0 = l0 * c0f + ls0; l1 = l1 * c1f + ls1;
#pragma unroll
            for (int t = 0; t < 8; t++) {
                acc[t][0] *= c0f; acc[t][1] *= c0f;
                acc[t][2] *= c1f; acc[t][3] *= c1f;
            }
        }

#pragma unroll
        for (int kc = 0; kc < 4; kc++) {
            uint32_t pah[4];
            pah[0] = pack_h(s[2 * kc][0],     s[2 * kc][1]);
            pah[1] = pack_h(s[2 * kc][2],     s[2 * kc][3]);
            pah[2] = pack_h(s[2 * kc + 1][0], s[2 * kc + 1][1]);
            pah[3] = pack_h(s[2 * kc + 1][2], s[2 * kc + 1][3]);
            const int vrow = kc * 16 + (((lane >> 3) & 1) << 3) + (lane & 7);
            const int vup = lane >> 4;
#pragma unroll
            for (int g = 0; g < 4; g++) {
                int u = (g * 2 + vup) ^ (vrow & 7);
                uint32_t off = (uint32_t)(vrow * 128 + u * 16);
                uint32_t vb[4];
                ldmx4t(vb, vbase + off);
                mma_f32(acc[2 * g],     pah, &vb[0]);
                mma_f32(acc[2 * g + 1], pah, &vb[2]);
            }
        }
        __syncthreads();
    }

    l0 += __shfl_xor_sync(0xffffffffu, l0, 1);
    l0 += __shfl_xor_sync(0xffffffffu, l0, 2);
    l1 += __shfl_xor_sync(0xffffffffu, l1, 1);
    l1 += __shfl_xor_sync(0xffffffffu, l1, 2);
    const float inv0 = 1.f / l0, inv1 = 1.f / l1;
    const size_t o0 = ((size_t)(b * SS) + gq0) * DM + h * HD;
    const size_t o1 = ((size_t)(b * SS) + gq1) * DM + h * HD;
#pragma unroll
    for (int t = 0; t < 8; t++) {
        int d = t * 8 + 2 * (lane & 3);
        *(uint32_t*)(g_A_h + o0 + d) = pack_h(acc[t][0] * inv0, acc[t][1] * inv0);
        *(uint32_t*)(g_A_h + o1 + d) = pack_h(acc[t][2] * inv1, acc[t][3] * inv1);
    }
}

static const int GEMM_SMEM = 65536;
static const int ATTN_SMEM = 40960;

extern "C" void kernel_launch(void* const* d_in, const int* in_sizes, int n_in,
                              void* d_out, int out_size)
{
    const float* Xq  = (const float*)d_in[0];
    const float* Xkv = (const float*)d_in[1];
    const int*   msk = (const int*)d_in[2];
    const float* Wq  = (const float*)d_in[3];
    const float* bq  = (const float*)d_in[4];
    const float* Wk  = (const float*)d_in[5];
    const float* bk  = (const float*)d_in[6];
    const float* Wv  = (const float*)d_in[7];
    const float* bv  = (const float*)d_in[8];
    const float* Wo  = (const float*)d_in[9];
    const float* bo  = (const float*)d_in[10];
    float* out = (float*)d_out;

    cudaFuncSetAttribute(gemm_qkv, cudaFuncAttributeMaxDynamicSharedMemorySize, GEMM_SMEM);
    cudaFuncSetAttribute(gemm_o,   cudaFuncAttributeMaxDynamicSharedMemorySize, GEMM_SMEM);
    cudaFuncSetAttribute(attn_tc,  cudaFuncAttributeMaxDynamicSharedMemorySize, ATTN_SMEM);

    const int n4x = NTOK * DM / 4;
    const int n4w = DM * DM / 4;

    split_x<<<dim3(n4x / 256, 2), 256>>>(Xq, Xkv);
    split_w<<<dim3(n4w / 256, 4), 256>>>(Wq, Wk, Wv, Wo);
    mask_pack<<<BB * SS * (SS / 32) / 256, 256>>>(msk);

    gemm_qkv<<<dim3(DM / 128, NTOK / 128, 3), 256, GEMM_SMEM>>>(bq, bk, bv);
    attn_tc<<<dim3(SS / 64, BB * NH), 128, ATTN_SMEM>>>();
    gemm_o<<<dim3(DM / 128, NTOK / 128), 256, GEMM_SMEM>>>(bo, out);
}